// round 3
// baseline (speedup 1.0000x reference)
#include <cuda_runtime.h>
#include <cuda_bf16.h>
#include <cuda_fp16.h>
#include <cstdint>
#include <cstddef>

// ---------------- problem constants ----------------
#define H_DIM   2048
#define V_DIM   32000
#define NROWS   2048            // B*T rows per model
#define BM      256
#define BN      128
#define BK      64
#define NTILES  250             // 32000 / 128
#define MGROUPS 8               // 2048 / 256
#define NSPLIT  9               // 2*8*9 = 144 CTAs
#define KCH     32              // 2048 / 64 K-chunks per n-tile
#define THREADS 512
#define L2E     1.4426950408889634f
#define LN2     0.6931471805599453f

// ---------------- SMEM ----------------
#define A_BYTES (BM * 128)              // 32768 (256 rows x 128B)
#define B_BYTES (BN * 128)              // 16384
#define BUF_B   (A_BYTES + B_BYTES)     // 49152
#define SMEM_TOTAL (3 * BUF_B)          // 147456

// ---------------- device scratch ----------------
__device__ __nv_bfloat16 g_Wb[2][(size_t)V_DIM * H_DIM];
__device__ __nv_bfloat16 g_xb[2][(size_t)NROWS * H_DIM];  // pre-scaled by log2(e)
__device__ float2 g_part[2 * NROWS * NSPLIT * 2];         // 18 partials/row
__device__ float  g_logp[2 * NROWS];
__device__ float  g_maskf[2 * NROWS];
__device__ int    g_y64;

// ---------------- helpers ----------------
__device__ __forceinline__ uint32_t smem_u32(const void* p) {
    uint32_t a;
    asm("{ .reg .u64 t; cvta.to.shared.u64 t, %1; cvt.u32.u64 %0, t; }"
        : "=r"(a) : "l"(p));
    return a;
}

#define SW128(o) ((o) ^ (((o) >> 3) & 0x70))

__device__ __forceinline__ void cp_async16(uint32_t saddr, const void* gaddr) {
    asm volatile("cp.async.cg.shared.global [%0], [%1], 16;"
                 :: "r"(saddr), "l"(gaddr) : "memory");
}
#define CP_COMMIT() asm volatile("cp.async.commit_group;" ::: "memory")
template<int N> __device__ __forceinline__ void cp_wait() {
    asm volatile("cp.async.wait_group %0;" :: "n"(N) : "memory");
}

__device__ __forceinline__ void ldsm_x4(uint32_t (&r)[4], uint32_t addr) {
    asm volatile("ldmatrix.sync.aligned.m8n8.x4.shared.b16 {%0,%1,%2,%3}, [%4];"
        : "=r"(r[0]), "=r"(r[1]), "=r"(r[2]), "=r"(r[3]) : "r"(addr));
}

__device__ __forceinline__ void mma16816(float (&d)[4], const uint32_t (&a)[4],
                                         uint32_t b0, uint32_t b1) {
    asm volatile(
        "mma.sync.aligned.m16n8k16.row.col.f32.bf16.bf16.f32 "
        "{%0,%1,%2,%3}, {%4,%5,%6,%7}, {%8,%9}, {%0,%1,%2,%3};"
        : "+f"(d[0]), "+f"(d[1]), "+f"(d[2]), "+f"(d[3])
        : "r"(a[0]), "r"(a[1]), "r"(a[2]), "r"(a[3]), "r"(b0), "r"(b1));
}

// ---------------- fp32 -> bf16 conversion (x gets log2(e) scale) ----------
__global__ void cvt_kernel(const float* __restrict__ src, int isW, int model,
                           int n4, float scale) {
    int i = blockIdx.x * blockDim.x + threadIdx.x;
    if (i >= n4) return;
    __nv_bfloat16* dst = isW ? g_Wb[model] : g_xb[model];
    float4 v = reinterpret_cast<const float4*>(src)[i];
    __nv_bfloat162 lo = __floats2bfloat162_rn(v.x * scale, v.y * scale);
    __nv_bfloat162 hi = __floats2bfloat162_rn(v.z * scale, v.w * scale);
    uint2 o;
    o.x = *reinterpret_cast<unsigned*>(&lo);
    o.y = *reinterpret_cast<unsigned*>(&hi);
    reinterpret_cast<uint2*>(dst)[i] = o;
}

// ---------------- y dtype detect (int32 vs int64) ----------------
__global__ void detect_kernel(const int* __restrict__ y32) {
    if (threadIdx.x == 0) {
        int z = 0;
        for (int i = 0; i < 32; i++)
            if (y32[2 * i + 1] == 0) z++;
        g_y64 = (z >= 28) ? 1 : 0;
    }
}

// ---------------- chunk loader: A (256x64) + B (128x64) bf16 ----------
__device__ __forceinline__ void load_chunk(
    uint32_t dstbase,
    const __nv_bfloat16* __restrict__ xrows,
    const __nv_bfloat16* __restrict__ Wb,
    int nt, int kc, int tid)
{
    #pragma unroll
    for (int j = 0; j < 4; j++) {                 // A: 2048 x 16B segs
        int idx = j * THREADS + tid;
        int row = idx >> 3, seg = idx & 7;
        uint32_t sa = dstbase + SW128((uint32_t)(row * 128 + seg * 16));
        cp_async16(sa, xrows + (size_t)row * H_DIM + kc * BK + seg * 8);
    }
    #pragma unroll
    for (int j = 0; j < 2; j++) {                 // B: 1024 x 16B segs
        int idx = j * THREADS + tid;
        int row = idx >> 3, seg = idx & 7;
        uint32_t sa = dstbase + A_BYTES + SW128((uint32_t)(row * 128 + seg * 16));
        cp_async16(sa, Wb + (size_t)(nt * BN + row) * H_DIM + kc * BK + seg * 8);
    }
    CP_COMMIT();
}

// ---------------- main fused GEMM + online LSE (log2 domain) ----------
__global__ void __launch_bounds__(THREADS, 1) dpo_main_kernel() {
    extern __shared__ char smem[];
    const uint32_t sb = smem_u32(smem);
    const int tid = threadIdx.x;
    const int lid = tid & 31;
    const int wid = tid >> 5;
    const int wm  = wid >> 1;       // 0..7 (M position)
    const int wn  = wid & 1;        // 0..1 (N position)

    const int cta    = blockIdx.x;
    const int model  = cta / (MGROUPS * NSPLIT);
    const int rest   = cta % (MGROUPS * NSPLIT);
    const int mgroup = rest / NSPLIT;
    const int split  = rest % NSPLIT;

    const __nv_bfloat16* __restrict__ Wb = g_Wb[model];
    const __nv_bfloat16* __restrict__ xrows =
        g_xb[model] + (size_t)(mgroup * BM) * H_DIM;

    const int ntcount = (NTILES - split + NSPLIT - 1) / NSPLIT;
    const int total   = ntcount * KCH;

    // ldmatrix address components
    const int a_row0 = wm * 32 + (lid & 15);
    const uint32_t a_kh = (uint32_t)((lid >> 4) * 16);
    const int b_row0 = wn * 64 + (lid & 7) + ((lid >> 4) << 3);
    const uint32_t b_kh = (uint32_t)(((lid >> 3) & 1) * 16);

    float acc[2][8][4];
    #pragma unroll
    for (int i = 0; i < 2; i++)
        #pragma unroll
        for (int j = 0; j < 8; j++)
            #pragma unroll
            for (int q = 0; q < 4; q++) acc[i][j][q] = 0.f;

    float run_m[4], run_s[4];
    #pragma unroll
    for (int q = 0; q < 4; q++) { run_m[q] = -3.0e38f; run_s[q] = 0.f; }

    // prologue: chunks 0, 1
    load_chunk(sb + 0 * BUF_B, xrows, Wb, split, 0, tid);
    if (total > 1)
        load_chunk(sb + 1 * BUF_B, xrows, Wb, split + NSPLIT * (1 >> 5), 1, tid);

    for (int c = 0; c < total; c++) {
        if (c + 2 < total) cp_wait<1>(); else cp_wait<0>();
        __syncthreads();

        // prefetch chunk c+2 (overwrites buffer (c-1)%3, safe after barrier)
        if (c + 2 < total) {
            int c2 = c + 2;
            load_chunk(sb + (c2 % 3) * BUF_B, xrows, Wb,
                       split + NSPLIT * (c2 >> 5), c2 & 31, tid);
        }

        const uint32_t bufbase = sb + (c % 3) * BUF_B;
        #pragma unroll
        for (int ks = 0; ks < 4; ks++) {
            uint32_t a_frag[2][4], b_frag[4][4];
            #pragma unroll
            for (int i = 0; i < 2; i++)
                ldsm_x4(a_frag[i], bufbase +
                    SW128((uint32_t)((a_row0 + i * 16) * 128) + a_kh + ks * 32));
            #pragma unroll
            for (int j2 = 0; j2 < 4; j2++)
                ldsm_x4(b_frag[j2], bufbase + A_BYTES +
                    SW128((uint32_t)((b_row0 + j2 * 16) * 128) + b_kh + ks * 32));
            #pragma unroll
            for (int i = 0; i < 2; i++)
                #pragma unroll
                for (int j = 0; j < 8; j++)
                    mma16816(acc[i][j], a_frag[i],
                             b_frag[j >> 1][(j & 1) * 2],
                             b_frag[j >> 1][(j & 1) * 2 + 1]);
        }

        if ((c & 31) == 31) {
            // epilogue: online max / sum-exp2 for this n-tile (128 cols)
            #pragma unroll
            for (int i = 0; i < 2; i++) {
                #pragma unroll
                for (int rh = 0; rh < 2; rh++) {
                    const int rr = i * 2 + rh;
                    float rmax = -3.0e38f;
                    #pragma unroll
                    for (int j = 0; j < 8; j++)
                        rmax = fmaxf(rmax, fmaxf(acc[i][j][rh * 2],
                                                 acc[i][j][rh * 2 + 1]));
                    rmax = fmaxf(rmax, __shfl_xor_sync(0xffffffffu, rmax, 1));
                    rmax = fmaxf(rmax, __shfl_xor_sync(0xffffffffu, rmax, 2));
                    const float mnew = fmaxf(run_m[rr], rmax);
                    __half2 s2 = __float2half2_rn(0.f);
                    #pragma unroll
                    for (int j = 0; j < 8; j++) {
                        float d0 = acc[i][j][rh * 2]     - mnew;
                        float d1 = acc[i][j][rh * 2 + 1] - mnew;
                        s2 = __hadd2(s2, h2exp2(__floats2half2_rn(d0, d1)));
                    }
                    float2 sf = __half22float2(s2);
                    float st = sf.x + sf.y;
                    st += __shfl_xor_sync(0xffffffffu, st, 1);
                    st += __shfl_xor_sync(0xffffffffu, st, 2);
                    run_s[rr] = run_s[rr] * exp2f(run_m[rr] - mnew) + st;
                    run_m[rr] = mnew;
                }
            }
            #pragma unroll
            for (int i = 0; i < 2; i++)
                #pragma unroll
                for (int j = 0; j < 8; j++)
                    #pragma unroll
                    for (int q = 0; q < 4; q++) acc[i][j][q] = 0.f;
        }
    }

    // write per-(row, split*2+wn) partials
    if ((lid & 3) == 0) {
        #pragma unroll
        for (int i = 0; i < 2; i++)
            #pragma unroll
            for (int rh = 0; rh < 2; rh++) {
                int grow = mgroup * BM + wm * 32 + i * 16 + rh * 8 + (lid >> 2);
                g_part[((size_t)(model * NROWS + grow) * NSPLIT + split) * 2 + wn] =
                    make_float2(run_m[i * 2 + rh], run_s[i * 2 + rh]);
            }
    }
}

// ---------------- combine partials + token dot -> per-row logp -------
__global__ void reduce_kernel(const void* __restrict__ yp) {
    int wid = threadIdx.x >> 5, lid = threadIdx.x & 31;
    int row_all = blockIdx.x * 8 + wid;        // 512 blocks -> 4096 rows
    if (row_all >= 2 * NROWS) return;
    int model = row_all >> 11;
    int r     = row_all & (NROWS - 1);

    long long yv = g_y64 ? ((const long long*)yp)[r]
                         : (long long)((const int*)yp)[r];
    bool mask = (yv != -100);
    int safe = mask ? (int)yv : 0;

    // token logit in log2 domain (x pre-scaled by log2 e)
    const __nv_bfloat162* xr =
        (const __nv_bfloat162*)(g_xb[model] + (size_t)r * H_DIM);
    const __nv_bfloat162* wr =
        (const __nv_bfloat162*)(g_Wb[model] + (size_t)safe * H_DIM);
    float acc = 0.f;
    #pragma unroll 8
    for (int t = 0; t < 32; t++) {
        int i = t * 32 + lid;
        float2 a = __bfloat1622float2(xr[i]);
        float2 b = __bfloat1622float2(wr[i]);
        acc = fmaf(a.x, b.x, acc);
        acc = fmaf(a.y, b.y, acc);
    }
    #pragma unroll
    for (int off = 16; off; off >>= 1)
        acc += __shfl_xor_sync(0xffffffffu, acc, off);

    const float2* pp = &g_part[(size_t)(model * NROWS + r) * NSPLIT * 2];
    float M = -3.0e38f;
    #pragma unroll
    for (int s = 0; s < NSPLIT * 2; s++) M = fmaxf(M, pp[s].x);
    float S = 0.f;
    #pragma unroll
    for (int s = 0; s < NSPLIT * 2; s++) S += pp[s].y * exp2f(pp[s].x - M);
    float lse2 = M + log2f(S);
    if (lid == 0) {
        g_logp[row_all]  = mask ? LN2 * (acc - lse2) : 0.f;
        g_maskf[row_all] = mask ? 1.f : 0.f;
    }
}

// ---------------- final loss ----------------
__global__ void final_kernel(float* __restrict__ out) {
    __shared__ float avg[8];
    int wid = threadIdx.x >> 5, lid = threadIdx.x & 31;
    float sl = 0.f, sm = 0.f;
    for (int i = lid; i < 512; i += 32) {
        sl += g_logp[wid * 512 + i];
        sm += g_maskf[wid * 512 + i];
    }
    #pragma unroll
    for (int off = 16; off; off >>= 1) {
        sl += __shfl_xor_sync(0xffffffffu, sl, off);
        sm += __shfl_xor_sync(0xffffffffu, sm, off);
    }
    if (lid == 0) avg[wid] = (sm > 0.f) ? (sl / sm) : 0.f;
    __syncthreads();
    if (threadIdx.x == 0) {
        const float BETA = 0.1f;
        float loss = 0.f;
        for (int b = 0; b < 4; b++) {
            float lr = avg[b] - avg[4 + b];       // policy - ref
            float z = (b < 2) ? (BETA * lr) : (-BETA * lr);
            float sig = 1.f / (1.f + expf(-z));
            loss += 1.f - sig;
        }
        out[0] = loss / 2.f;
    }
}

// ---------------- launcher ----------------
extern "C" void kernel_launch(void* const* d_in, const int* in_sizes, int n_in,
                              void* d_out, int out_size) {
    const float* x  = (const float*)d_in[0];
    const float* rx = (const float*)d_in[1];
    const void*  y  = d_in[2];
    const float* W  = (const float*)d_in[3];
    const float* rW = (const float*)d_in[4];
    float* out = (float*)d_out;

    cudaFuncSetAttribute(dpo_main_kernel,
                         cudaFuncAttributeMaxDynamicSharedMemorySize, SMEM_TOTAL);

    cvt_kernel<<<4096,  256>>>(x,  0, 0, NROWS * H_DIM / 4, L2E);
    cvt_kernel<<<4096,  256>>>(rx, 0, 1, NROWS * H_DIM / 4, L2E);
    cvt_kernel<<<64000, 256>>>(W,  1, 0, V_DIM * H_DIM / 4, 1.0f);
    cvt_kernel<<<64000, 256>>>(rW, 1, 1, V_DIM * H_DIM / 4, 1.0f);
    detect_kernel<<<1, 32>>>((const int*)y);
    dpo_main_kernel<<<144, THREADS, SMEM_TOTAL>>>();
    reduce_kernel<<<512, 256>>>(y);
    final_kernel<<<1, 256>>>(out);
}

// round 4
// speedup vs baseline: 1.0261x; 1.0261x over previous
#include <cuda_runtime.h>
#include <cuda_bf16.h>
#include <cuda_fp16.h>
#include <cstdint>
#include <cstddef>

// ---------------- problem constants ----------------
#define H_DIM   2048
#define V_DIM   32000
#define NROWS   2048            // B*T rows per model
#define BM      256
#define BN      128
#define BK      64
#define NTILES  250             // 32000 / 128
#define MGROUPS 8               // 2048 / 256
#define NSPLIT  9               // 2*8*9 = 144 CTAs
#define KCH     32              // K-chunks per n-tile
#define THREADS 512
#define L2E     1.4426950408889634f
#define LN2     0.6931471805599453f

// ---------------- SMEM ----------------
#define A_BYTES (BM * 128)              // 32768
#define B_BYTES (BN * 128)              // 16384
#define BUF_B   (A_BYTES + B_BYTES)     // 49152
#define SMEM_TOTAL (3 * BUF_B)          // 147456

// ---------------- device scratch ----------------
__device__ __nv_bfloat16 g_Wb[2][(size_t)V_DIM * H_DIM];
__device__ __nv_bfloat16 g_xb[2][(size_t)NROWS * H_DIM];  // pre-scaled by log2(e)
__device__ float2 g_part[2 * NROWS * NSPLIT * 2];
__device__ float  g_logp[2 * NROWS];
__device__ float  g_maskf[2 * NROWS];
__device__ int    g_y64;

// ---------------- helpers ----------------
__device__ __forceinline__ uint32_t smem_u32(const void* p) {
    uint32_t a;
    asm("{ .reg .u64 t; cvta.to.shared.u64 t, %1; cvt.u32.u64 %0, t; }"
        : "=r"(a) : "l"(p));
    return a;
}

#define SW128(o) ((o) ^ (((o) >> 3) & 0x70))

__device__ __forceinline__ void cp_async16(uint32_t saddr, const void* gaddr) {
    asm volatile("cp.async.cg.shared.global [%0], [%1], 16;"
                 :: "r"(saddr), "l"(gaddr) : "memory");
}
#define CP_COMMIT() asm volatile("cp.async.commit_group;" ::: "memory")
template<int N> __device__ __forceinline__ void cp_wait() {
    asm volatile("cp.async.wait_group %0;" :: "n"(N) : "memory");
}

__device__ __forceinline__ void ldsm_x4(uint32_t (&r)[4], uint32_t addr) {
    asm volatile("ldmatrix.sync.aligned.m8n8.x4.shared.b16 {%0,%1,%2,%3}, [%4];"
        : "=r"(r[0]), "=r"(r[1]), "=r"(r[2]), "=r"(r[3]) : "r"(addr));
}

__device__ __forceinline__ void mma16816(float (&d)[4], const uint32_t (&a)[4],
                                         uint32_t b0, uint32_t b1) {
    asm volatile(
        "mma.sync.aligned.m16n8k16.row.col.f32.bf16.bf16.f32 "
        "{%0,%1,%2,%3}, {%4,%5,%6,%7}, {%8,%9}, {%0,%1,%2,%3};"
        : "+f"(d[0]), "+f"(d[1]), "+f"(d[2]), "+f"(d[3])
        : "r"(a[0]), "r"(a[1]), "r"(a[2]), "r"(a[3]), "r"(b0), "r"(b1));
}

// ---------------- fp32 -> bf16 conversion (x gets log2(e) scale) ----------
__global__ void cvt_kernel(const float* __restrict__ src, int isW, int model,
                           int n4, float scale) {
    int i = blockIdx.x * blockDim.x + threadIdx.x;
    if (i >= n4) return;
    __nv_bfloat16* dst = isW ? g_Wb[model] : g_xb[model];
    float4 v = reinterpret_cast<const float4*>(src)[i];
    __nv_bfloat162 lo = __floats2bfloat162_rn(v.x * scale, v.y * scale);
    __nv_bfloat162 hi = __floats2bfloat162_rn(v.z * scale, v.w * scale);
    uint2 o;
    o.x = *reinterpret_cast<unsigned*>(&lo);
    o.y = *reinterpret_cast<unsigned*>(&hi);
    reinterpret_cast<uint2*>(dst)[i] = o;
}

// ---------------- y dtype detect (int32 vs int64) ----------------
__global__ void detect_kernel(const int* __restrict__ y32) {
    if (threadIdx.x == 0) {
        int z = 0;
        for (int i = 0; i < 32; i++)
            if (y32[2 * i + 1] == 0) z++;
        g_y64 = (z >= 28) ? 1 : 0;
    }
}

// ---------------- chunk loader: A (256x64) + B (128x64) bf16 ----------
__device__ __forceinline__ void load_chunk(
    uint32_t dstbase,
    const __nv_bfloat16* __restrict__ xrows,
    const __nv_bfloat16* __restrict__ Wb,
    int nt, int kc, int tid)
{
    #pragma unroll
    for (int j = 0; j < 4; j++) {                 // A: 2048 x 16B segs
        int idx = j * THREADS + tid;
        int row = idx >> 3, seg = idx & 7;
        uint32_t sa = dstbase + SW128((uint32_t)(row * 128 + seg * 16));
        cp_async16(sa, xrows + (size_t)row * H_DIM + kc * BK + seg * 8);
    }
    #pragma unroll
    for (int j = 0; j < 2; j++) {                 // B: 1024 x 16B segs
        int idx = j * THREADS + tid;
        int row = idx >> 3, seg = idx & 7;
        uint32_t sa = dstbase + A_BYTES + SW128((uint32_t)(row * 128 + seg * 16));
        cp_async16(sa, Wb + (size_t)(nt * BN + row) * H_DIM + kc * BK + seg * 8);
    }
    CP_COMMIT();
}

// ---------------- main fused GEMM + online LSE (log2 domain) ----------
__global__ void __launch_bounds__(THREADS, 1) dpo_main_kernel() {
    extern __shared__ char smem[];
    const uint32_t sb = smem_u32(smem);
    const int tid = threadIdx.x;
    const int lid = tid & 31;
    const int wid = tid >> 5;
    const int wm  = wid >> 1;       // 0..7 (M position)
    const int wn  = wid & 1;        // 0..1 (N position)

    const int cta    = blockIdx.x;
    const int model  = cta / (MGROUPS * NSPLIT);
    const int rest   = cta % (MGROUPS * NSPLIT);
    const int mgroup = rest / NSPLIT;
    const int split  = rest % NSPLIT;

    const __nv_bfloat16* __restrict__ Wb = g_Wb[model];
    const __nv_bfloat16* __restrict__ xrows =
        g_xb[model] + (size_t)(mgroup * BM) * H_DIM;

    const int ntcount = (NTILES - split + NSPLIT - 1) / NSPLIT;
    const int total   = ntcount * KCH;

    // precomputed swizzled base offsets (relative to buffer base)
    const int a_row0 = wm * 32 + (lid & 15);
    const uint32_t a_kh = (uint32_t)((lid >> 4) * 16);
    const int b_row0 = wn * 64 + (lid & 7) + ((lid >> 4) << 3);
    const uint32_t b_kh = (uint32_t)(((lid >> 3) & 1) * 16);

    uint32_t a_off[2], b_off[4];
    #pragma unroll
    for (int i = 0; i < 2; i++)
        a_off[i] = SW128((uint32_t)((a_row0 + i * 16) * 128) + a_kh);
    #pragma unroll
    for (int j = 0; j < 4; j++)
        b_off[j] = SW128((uint32_t)((b_row0 + j * 16) * 128) + b_kh) + A_BYTES;

    float acc[2][8][4];
    #pragma unroll
    for (int i = 0; i < 2; i++)
        #pragma unroll
        for (int j = 0; j < 8; j++)
            #pragma unroll
            for (int q = 0; q < 4; q++) acc[i][j][q] = 0.f;

    float run_m[4], run_s[4];
    #pragma unroll
    for (int q = 0; q < 4; q++) { run_m[q] = -3.0e38f; run_s[q] = 0.f; }

    load_chunk(sb + 0 * BUF_B, xrows, Wb, split, 0, tid);
    if (total > 1)
        load_chunk(sb + 1 * BUF_B, xrows, Wb, split, 1, tid);

    #pragma unroll 1
    for (int c = 0; c < total; c++) {
        if (c + 2 < total) cp_wait<1>(); else cp_wait<0>();
        __syncthreads();

        // prefetch chunk c+2 (buffer (c+2)%3 was consumed at c-1; safe post-barrier)
        if (c + 2 < total) {
            int c2 = c + 2;
            load_chunk(sb + (c2 % 3) * BUF_B, xrows, Wb,
                       split + NSPLIT * (c2 >> 5), c2 & 31, tid);
        }

        const uint32_t bufbase = sb + (c % 3) * BUF_B;
        #pragma unroll
        for (int ks = 0; ks < 4; ks++) {
            const uint32_t kx = (uint32_t)(ks << 5);
            uint32_t a_frag[2][4];
            ldsm_x4(a_frag[0], (bufbase + a_off[0]) ^ kx);
            ldsm_x4(a_frag[1], (bufbase + a_off[1]) ^ kx);
            uint32_t bcur[4], bnext[4];
            ldsm_x4(bcur, (bufbase + b_off[0]) ^ kx);
            #pragma unroll
            for (int j2 = 0; j2 < 4; j2++) {
                if (j2 < 3) ldsm_x4(bnext, (bufbase + b_off[j2 + 1]) ^ kx);
                #pragma unroll
                for (int i = 0; i < 2; i++) {
                    mma16816(acc[i][j2 * 2],     a_frag[i], bcur[0], bcur[1]);
                    mma16816(acc[i][j2 * 2 + 1], a_frag[i], bcur[2], bcur[3]);
                }
                #pragma unroll
                for (int q = 0; q < 4; q++) bcur[q] = bnext[q];
            }
        }

        if ((c & 31) == 31) {
            // epilogue: online max / sum-exp2 for this n-tile (128 cols)
            #pragma unroll
            for (int i = 0; i < 2; i++) {
                #pragma unroll
                for (int rh = 0; rh < 2; rh++) {
                    const int rr = i * 2 + rh;
                    float rmax = -3.0e38f;
                    #pragma unroll
                    for (int j = 0; j < 8; j++)
                        rmax = fmaxf(rmax, fmaxf(acc[i][j][rh * 2],
                                                 acc[i][j][rh * 2 + 1]));
                    rmax = fmaxf(rmax, __shfl_xor_sync(0xffffffffu, rmax, 1));
                    rmax = fmaxf(rmax, __shfl_xor_sync(0xffffffffu, rmax, 2));
                    const float mnew = fmaxf(run_m[rr], rmax);
                    __half2 s2 = __float2half2_rn(0.f);
                    #pragma unroll
                    for (int j = 0; j < 8; j++) {
                        float d0 = acc[i][j][rh * 2]     - mnew;
                        float d1 = acc[i][j][rh * 2 + 1] - mnew;
                        s2 = __hadd2(s2, h2exp2(__floats2half2_rn(d0, d1)));
                    }
                    float2 sf = __half22float2(s2);
                    float st = sf.x + sf.y;
                    st += __shfl_xor_sync(0xffffffffu, st, 1);
                    st += __shfl_xor_sync(0xffffffffu, st, 2);
                    run_s[rr] = run_s[rr] * exp2f(run_m[rr] - mnew) + st;
                    run_m[rr] = mnew;
                }
            }
            #pragma unroll
            for (int i = 0; i < 2; i++)
                #pragma unroll
                for (int j = 0; j < 8; j++)
                    #pragma unroll
                    for (int q = 0; q < 4; q++) acc[i][j][q] = 0.f;
        }
    }

    // write per-(row, split*2+wn) partials
    if ((lid & 3) == 0) {
        #pragma unroll
        for (int i = 0; i < 2; i++)
            #pragma unroll
            for (int rh = 0; rh < 2; rh++) {
                int grow = mgroup * BM + wm * 32 + i * 16 + rh * 8 + (lid >> 2);
                g_part[((size_t)(model * NROWS + grow) * NSPLIT + split) * 2 + wn] =
                    make_float2(run_m[i * 2 + rh], run_s[i * 2 + rh]);
            }
    }
}

// ---------------- combine partials + token dot -> per-row logp -------
__global__ void reduce_kernel(const void* __restrict__ yp) {
    int wid = threadIdx.x >> 5, lid = threadIdx.x & 31;
    int row_all = blockIdx.x * 8 + wid;
    if (row_all >= 2 * NROWS) return;
    int model = row_all >> 11;
    int r     = row_all & (NROWS - 1);

    long long yv = g_y64 ? ((const long long*)yp)[r]
                         : (long long)((const int*)yp)[r];
    bool mask = (yv != -100);
    int safe = mask ? (int)yv : 0;

    const __nv_bfloat162* xr =
        (const __nv_bfloat162*)(g_xb[model] + (size_t)r * H_DIM);
    const __nv_bfloat162* wr =
        (const __nv_bfloat162*)(g_Wb[model] + (size_t)safe * H_DIM);
    float acc = 0.f;
    #pragma unroll 8
    for (int t = 0; t < 32; t++) {
        int i = t * 32 + lid;
        float2 a = __bfloat1622float2(xr[i]);
        float2 b = __bfloat1622float2(wr[i]);
        acc = fmaf(a.x, b.x, acc);
        acc = fmaf(a.y, b.y, acc);
    }
    #pragma unroll
    for (int off = 16; off; off >>= 1)
        acc += __shfl_xor_sync(0xffffffffu, acc, off);

    const float2* pp = &g_part[(size_t)(model * NROWS + r) * NSPLIT * 2];
    float M = -3.0e38f;
    #pragma unroll
    for (int s = 0; s < NSPLIT * 2; s++) M = fmaxf(M, pp[s].x);
    float S = 0.f;
    #pragma unroll
    for (int s = 0; s < NSPLIT * 2; s++) S += pp[s].y * exp2f(pp[s].x - M);
    float lse2 = M + log2f(S);
    if (lid == 0) {
        g_logp[row_all]  = mask ? LN2 * (acc - lse2) : 0.f;
        g_maskf[row_all] = mask ? 1.f : 0.f;
    }
}

// ---------------- final loss ----------------
__global__ void final_kernel(float* __restrict__ out) {
    __shared__ float avg[8];
    int wid = threadIdx.x >> 5, lid = threadIdx.x & 31;
    float sl = 0.f, sm = 0.f;
    for (int i = lid; i < 512; i += 32) {
        sl += g_logp[wid * 512 + i];
        sm += g_maskf[wid * 512 + i];
    }
    #pragma unroll
    for (int off = 16; off; off >>= 1) {
        sl += __shfl_xor_sync(0xffffffffu, sl, off);
        sm += __shfl_xor_sync(0xffffffffu, sm, off);
    }
    if (lid == 0) avg[wid] = (sm > 0.f) ? (sl / sm) : 0.f;
    __syncthreads();
    if (threadIdx.x == 0) {
        const float BETA = 0.1f;
        float loss = 0.f;
        for (int b = 0; b < 4; b++) {
            float lr = avg[b] - avg[4 + b];
            float z = (b < 2) ? (BETA * lr) : (-BETA * lr);
            float sig = 1.f / (1.f + expf(-z));
            loss += 1.f - sig;
        }
        out[0] = loss / 2.f;
    }
}

// ---------------- launcher ----------------
extern "C" void kernel_launch(void* const* d_in, const int* in_sizes, int n_in,
                              void* d_out, int out_size) {
    const float* x  = (const float*)d_in[0];
    const float* rx = (const float*)d_in[1];
    const void*  y  = d_in[2];
    const float* W  = (const float*)d_in[3];
    const float* rW = (const float*)d_in[4];
    float* out = (float*)d_out;

    cudaFuncSetAttribute(dpo_main_kernel,
                         cudaFuncAttributeMaxDynamicSharedMemorySize, SMEM_TOTAL);

    cvt_kernel<<<4096,  256>>>(x,  0, 0, NROWS * H_DIM / 4, L2E);
    cvt_kernel<<<4096,  256>>>(rx, 0, 1, NROWS * H_DIM / 4, L2E);
    cvt_kernel<<<64000, 256>>>(W,  1, 0, V_DIM * H_DIM / 4, 1.0f);
    cvt_kernel<<<64000, 256>>>(rW, 1, 1, V_DIM * H_DIM / 4, 1.0f);
    detect_kernel<<<1, 32>>>((const int*)y);
    dpo_main_kernel<<<144, THREADS, SMEM_TOTAL>>>();
    reduce_kernel<<<512, 256>>>(y);
    final_kernel<<<1, 256>>>(out);
}

// round 5
// speedup vs baseline: 1.0574x; 1.0304x over previous
#include <cuda_runtime.h>
#include <cuda_bf16.h>
#include <cuda_fp16.h>
#include <cstdint>
#include <cstddef>

// ---------------- problem constants ----------------
#define H_DIM   2048
#define V_DIM   32000
#define NROWS   2048            // B*T rows per model
#define BM      128
#define BN      128
#define BK      64
#define NTILES  250             // 32000 / 128
#define MGROUPS 16              // 2048 / 128
#define NSPLIT  9               // 2*16*9 = 288 CTAs (occ 2, one wave)
#define KCH     32              // K-chunks per n-tile
#define THREADS 256
#define L2E     1.4426950408889634f
#define LN2     0.6931471805599453f

// ---------------- SMEM ----------------
#define A_BYTES (BM * 128)              // 16384
#define B_BYTES (BN * 128)              // 16384
#define BUF_B   (A_BYTES + B_BYTES)     // 32768
#define SMEM_TOTAL (3 * BUF_B)          // 98304 -> 2 CTAs/SM

// ---------------- device scratch ----------------
__device__ __nv_bfloat16 g_Wb[2][(size_t)V_DIM * H_DIM];
__device__ __nv_bfloat16 g_xb[2][(size_t)NROWS * H_DIM];  // pre-scaled by log2(e)
__device__ float2 g_part[2 * NROWS * NSPLIT * 2];
__device__ float  g_logp[2 * NROWS];
__device__ float  g_maskf[2 * NROWS];
__device__ int    g_y64;

// ---------------- helpers ----------------
__device__ __forceinline__ uint32_t smem_u32(const void* p) {
    uint32_t a;
    asm("{ .reg .u64 t; cvta.to.shared.u64 t, %1; cvt.u32.u64 %0, t; }"
        : "=r"(a) : "l"(p));
    return a;
}

#define SW128(o) ((o) ^ (((o) >> 3) & 0x70))

__device__ __forceinline__ void cp_async16(uint32_t saddr, const void* gaddr) {
    asm volatile("cp.async.cg.shared.global [%0], [%1], 16;"
                 :: "r"(saddr), "l"(gaddr) : "memory");
}
#define CP_COMMIT() asm volatile("cp.async.commit_group;" ::: "memory")
template<int N> __device__ __forceinline__ void cp_wait() {
    asm volatile("cp.async.wait_group %0;" :: "n"(N) : "memory");
}

__device__ __forceinline__ void ldsm_x4(uint32_t (&r)[4], uint32_t addr) {
    asm volatile("ldmatrix.sync.aligned.m8n8.x4.shared.b16 {%0,%1,%2,%3}, [%4];"
        : "=r"(r[0]), "=r"(r[1]), "=r"(r[2]), "=r"(r[3]) : "r"(addr));
}

__device__ __forceinline__ void mma16816(float (&d)[4], const uint32_t (&a)[4],
                                         uint32_t b0, uint32_t b1) {
    asm volatile(
        "mma.sync.aligned.m16n8k16.row.col.f32.bf16.bf16.f32 "
        "{%0,%1,%2,%3}, {%4,%5,%6,%7}, {%8,%9}, {%0,%1,%2,%3};"
        : "+f"(d[0]), "+f"(d[1]), "+f"(d[2]), "+f"(d[3])
        : "r"(a[0]), "r"(a[1]), "r"(a[2]), "r"(a[3]), "r"(b0), "r"(b1));
}

// ---------------- fp32 -> bf16 conversion (x gets log2(e) scale) ----------
__global__ void cvt_kernel(const float* __restrict__ src, int isW, int model,
                           int n4, float scale) {
    int i = blockIdx.x * blockDim.x + threadIdx.x;
    if (i >= n4) return;
    __nv_bfloat16* dst = isW ? g_Wb[model] : g_xb[model];
    float4 v = reinterpret_cast<const float4*>(src)[i];
    __nv_bfloat162 lo = __floats2bfloat162_rn(v.x * scale, v.y * scale);
    __nv_bfloat162 hi = __floats2bfloat162_rn(v.z * scale, v.w * scale);
    uint2 o;
    o.x = *reinterpret_cast<unsigned*>(&lo);
    o.y = *reinterpret_cast<unsigned*>(&hi);
    reinterpret_cast<uint2*>(dst)[i] = o;
}

// ---------------- y dtype detect (int32 vs int64) ----------------
__global__ void detect_kernel(const int* __restrict__ y32) {
    if (threadIdx.x == 0) {
        int z = 0;
        for (int i = 0; i < 32; i++)
            if (y32[2 * i + 1] == 0) z++;
        g_y64 = (z >= 28) ? 1 : 0;
    }
}

// ---------------- chunk loader: A (128x64) + B (128x64) bf16 ----------
__device__ __forceinline__ void load_chunk(
    uint32_t dstbase,
    const __nv_bfloat16* __restrict__ xrows,
    const __nv_bfloat16* __restrict__ Wb,
    int nt, int kc, int tid)
{
    #pragma unroll
    for (int j = 0; j < 4; j++) {                 // A: 1024 x 16B segs
        int idx = j * THREADS + tid;
        int row = idx >> 3, seg = idx & 7;
        uint32_t sa = dstbase + SW128((uint32_t)(row * 128 + seg * 16));
        cp_async16(sa, xrows + (size_t)row * H_DIM + kc * BK + seg * 8);
    }
    #pragma unroll
    for (int j = 0; j < 4; j++) {                 // B: 1024 x 16B segs
        int idx = j * THREADS + tid;
        int row = idx >> 3, seg = idx & 7;
        uint32_t sa = dstbase + A_BYTES + SW128((uint32_t)(row * 128 + seg * 16));
        cp_async16(sa, Wb + (size_t)(nt * BN + row) * H_DIM + kc * BK + seg * 8);
    }
    CP_COMMIT();
}

// ---------------- main fused GEMM + online LSE (log2 domain) ----------
__global__ void __launch_bounds__(THREADS, 2) dpo_main_kernel() {
    extern __shared__ char smem[];
    const uint32_t sb = smem_u32(smem);
    const int tid = threadIdx.x;
    const int lid = tid & 31;
    const int wid = tid >> 5;
    const int wm  = wid >> 1;       // 0..3 (M position, 32 rows each)
    const int wn  = wid & 1;        // 0..1 (N position, 64 cols each)

    const int cta    = blockIdx.x;
    const int model  = cta / (MGROUPS * NSPLIT);
    const int rest   = cta % (MGROUPS * NSPLIT);
    const int mgroup = rest / NSPLIT;
    const int split  = rest % NSPLIT;

    const __nv_bfloat16* __restrict__ Wb = g_Wb[model];
    const __nv_bfloat16* __restrict__ xrows =
        g_xb[model] + (size_t)(mgroup * BM) * H_DIM;

    const int ntcount = (NTILES - split + NSPLIT - 1) / NSPLIT;
    const int total   = ntcount * KCH;

    // precomputed swizzled base offsets (relative to buffer base)
    const int a_row0 = wm * 32 + (lid & 15);
    const uint32_t a_kh = (uint32_t)((lid >> 4) * 16);
    const int b_row0 = wn * 64 + (lid & 7) + ((lid >> 4) << 3);
    const uint32_t b_kh = (uint32_t)(((lid >> 3) & 1) * 16);

    uint32_t a_off[2], b_off[4];
    #pragma unroll
    for (int i = 0; i < 2; i++)
        a_off[i] = SW128((uint32_t)((a_row0 + i * 16) * 128) + a_kh);
    #pragma unroll
    for (int j = 0; j < 4; j++)
        b_off[j] = SW128((uint32_t)((b_row0 + j * 16) * 128) + b_kh) + A_BYTES;

    float acc[2][8][4];
    #pragma unroll
    for (int i = 0; i < 2; i++)
        #pragma unroll
        for (int j = 0; j < 8; j++)
            #pragma unroll
            for (int q = 0; q < 4; q++) acc[i][j][q] = 0.f;

    float run_m[4], run_s[4];
    #pragma unroll
    for (int q = 0; q < 4; q++) { run_m[q] = -3.0e38f; run_s[q] = 0.f; }

    load_chunk(sb + 0 * BUF_B, xrows, Wb, split, 0, tid);
    if (total > 1)
        load_chunk(sb + 1 * BUF_B, xrows, Wb, split, 1, tid);

    #pragma unroll 1
    for (int c = 0; c < total; c++) {
        if (c + 2 < total) cp_wait<1>(); else cp_wait<0>();
        __syncthreads();

        // prefetch chunk c+2 (its buffer was consumed at c-1; safe post-barrier)
        if (c + 2 < total) {
            int c2 = c + 2;
            load_chunk(sb + (c2 % 3) * BUF_B, xrows, Wb,
                       split + NSPLIT * (c2 >> 5), c2 & 31, tid);
        }

        const uint32_t bufbase = sb + (c % 3) * BUF_B;
        #pragma unroll
        for (int ks = 0; ks < 4; ks++) {
            const uint32_t kx = (uint32_t)(ks << 5);
            uint32_t a_frag[2][4];
            ldsm_x4(a_frag[0], (bufbase + a_off[0]) ^ kx);
            ldsm_x4(a_frag[1], (bufbase + a_off[1]) ^ kx);
            uint32_t bcur[4], bnext[4];
            ldsm_x4(bcur, (bufbase + b_off[0]) ^ kx);
            #pragma unroll
            for (int j2 = 0; j2 < 4; j2++) {
                if (j2 < 3) ldsm_x4(bnext, (bufbase + b_off[j2 + 1]) ^ kx);
                #pragma unroll
                for (int i = 0; i < 2; i++) {
                    mma16816(acc[i][j2 * 2],     a_frag[i], bcur[0], bcur[1]);
                    mma16816(acc[i][j2 * 2 + 1], a_frag[i], bcur[2], bcur[3]);
                }
                #pragma unroll
                for (int q = 0; q < 4; q++) bcur[q] = bnext[q];
            }
        }

        if ((c & 31) == 31) {
            // epilogue: online max / sum-exp2 for this n-tile (128 cols)
            #pragma unroll
            for (int i = 0; i < 2; i++) {
                #pragma unroll
                for (int rh = 0; rh < 2; rh++) {
                    const int rr = i * 2 + rh;
                    float rmax = -3.0e38f;
                    #pragma unroll
                    for (int j = 0; j < 8; j++)
                        rmax = fmaxf(rmax, fmaxf(acc[i][j][rh * 2],
                                                 acc[i][j][rh * 2 + 1]));
                    rmax = fmaxf(rmax, __shfl_xor_sync(0xffffffffu, rmax, 1));
                    rmax = fmaxf(rmax, __shfl_xor_sync(0xffffffffu, rmax, 2));
                    const float mnew = fmaxf(run_m[rr], rmax);
                    __half2 s2 = __float2half2_rn(0.f);
                    #pragma unroll
                    for (int j = 0; j < 8; j++) {
                        float d0 = acc[i][j][rh * 2]     - mnew;
                        float d1 = acc[i][j][rh * 2 + 1] - mnew;
                        s2 = __hadd2(s2, h2exp2(__floats2half2_rn(d0, d1)));
                    }
                    float2 sf = __half22float2(s2);
                    float st = sf.x + sf.y;
                    st += __shfl_xor_sync(0xffffffffu, st, 1);
                    st += __shfl_xor_sync(0xffffffffu, st, 2);
                    run_s[rr] = run_s[rr] * exp2f(run_m[rr] - mnew) + st;
                    run_m[rr] = mnew;
                }
            }
            #pragma unroll
            for (int i = 0; i < 2; i++)
                #pragma unroll
                for (int j = 0; j < 8; j++)
                    #pragma unroll
                    for (int q = 0; q < 4; q++) acc[i][j][q] = 0.f;
        }
    }

    // write per-(row, split*2+wn) partials
    if ((lid & 3) == 0) {
        #pragma unroll
        for (int i = 0; i < 2; i++)
            #pragma unroll
            for (int rh = 0; rh < 2; rh++) {
                int grow = mgroup * BM + wm * 32 + i * 16 + rh * 8 + (lid >> 2);
                g_part[((size_t)(model * NROWS + grow) * NSPLIT + split) * 2 + wn] =
                    make_float2(run_m[i * 2 + rh], run_s[i * 2 + rh]);
            }
    }
}

// ---------------- combine partials + token dot -> per-row logp -------
__global__ void reduce_kernel(const void* __restrict__ yp) {
    int wid = threadIdx.x >> 5, lid = threadIdx.x & 31;
    int row_all = blockIdx.x * 8 + wid;
    if (row_all >= 2 * NROWS) return;
    int model = row_all >> 11;
    int r     = row_all & (NROWS - 1);

    long long yv = g_y64 ? ((const long long*)yp)[r]
                         : (long long)((const int*)yp)[r];
    bool mask = (yv != -100);
    int safe = mask ? (int)yv : 0;

    const __nv_bfloat162* xr =
        (const __nv_bfloat162*)(g_xb[model] + (size_t)r * H_DIM);
    const __nv_bfloat162* wr =
        (const __nv_bfloat162*)(g_Wb[model] + (size_t)safe * H_DIM);
    float acc = 0.f;
    #pragma unroll 8
    for (int t = 0; t < 32; t++) {
        int i = t * 32 + lid;
        float2 a = __bfloat1622float2(xr[i]);
        float2 b = __bfloat1622float2(wr[i]);
        acc = fmaf(a.x, b.x, acc);
        acc = fmaf(a.y, b.y, acc);
    }
    #pragma unroll
    for (int off = 16; off; off >>= 1)
        acc += __shfl_xor_sync(0xffffffffu, acc, off);

    const float2* pp = &g_part[(size_t)(model * NROWS + r) * NSPLIT * 2];
    float M = -3.0e38f;
    #pragma unroll
    for (int s = 0; s < NSPLIT * 2; s++) M = fmaxf(M, pp[s].x);
    float S = 0.f;
    #pragma unroll
    for (int s = 0; s < NSPLIT * 2; s++) S += pp[s].y * exp2f(pp[s].x - M);
    float lse2 = M + log2f(S);
    if (lid == 0) {
        g_logp[row_all]  = mask ? LN2 * (acc - lse2) : 0.f;
        g_maskf[row_all] = mask ? 1.f : 0.f;
    }
}

// ---------------- final loss ----------------
__global__ void final_kernel(float* __restrict__ out) {
    __shared__ float avg[8];
    int wid = threadIdx.x >> 5, lid = threadIdx.x & 31;
    float sl = 0.f, sm = 0.f;
    for (int i = lid; i < 512; i += 32) {
        sl += g_logp[wid * 512 + i];
        sm += g_maskf[wid * 512 + i];
    }
    #pragma unroll
    for (int off = 16; off; off >>= 1) {
        sl += __shfl_xor_sync(0xffffffffu, sl, off);
        sm += __shfl_xor_sync(0xffffffffu, sm, off);
    }
    if (lid == 0) avg[wid] = (sm > 0.f) ? (sl / sm) : 0.f;
    __syncthreads();
    if (threadIdx.x == 0) {
        const float BETA = 0.1f;
        float loss = 0.f;
        for (int b = 0; b < 4; b++) {
            float lr = avg[b] - avg[4 + b];
            float z = (b < 2) ? (BETA * lr) : (-BETA * lr);
            float sig = 1.f / (1.f + expf(-z));
            loss += 1.f - sig;
        }
        out[0] = loss / 2.f;
    }
}

// ---------------- launcher ----------------
extern "C" void kernel_launch(void* const* d_in, const int* in_sizes, int n_in,
                              void* d_out, int out_size) {
    const float* x  = (const float*)d_in[0];
    const float* rx = (const float*)d_in[1];
    const void*  y  = d_in[2];
    const float* W  = (const float*)d_in[3];
    const float* rW = (const float*)d_in[4];
    float* out = (float*)d_out;

    cudaFuncSetAttribute(dpo_main_kernel,
                         cudaFuncAttributeMaxDynamicSharedMemorySize, SMEM_TOTAL);

    cvt_kernel<<<4096,  256>>>(x,  0, 0, NROWS * H_DIM / 4, L2E);
    cvt_kernel<<<4096,  256>>>(rx, 0, 1, NROWS * H_DIM / 4, L2E);
    cvt_kernel<<<64000, 256>>>(W,  1, 0, V_DIM * H_DIM / 4, 1.0f);
    cvt_kernel<<<64000, 256>>>(rW, 1, 1, V_DIM * H_DIM / 4, 1.0f);
    detect_kernel<<<1, 32>>>((const int*)y);
    dpo_main_kernel<<<2 * MGROUPS * NSPLIT, THREADS, SMEM_TOTAL>>>();
    reduce_kernel<<<512, 256>>>(y);
    final_kernel<<<1, 256>>>(out);
}